// round 14
// baseline (speedup 1.0000x reference)
#include <cuda_runtime.h>
#include <cuda_bf16.h>

// Problem constants (fixed by setup_inputs)
#define T_TOK  8192
#define DIM    4096
#define KS     4
#define NSLOT  128
#define TOPK   1024
#define MAXL   4096   // worst case: all TOPK*KS writes land on one slot

// Scratch (no allocations allowed -> __device__ globals)
__device__ float g_imp[T_TOK];
__device__ int   g_slot_cnt[NSLOT];
__device__ int   g_slot_list[NSLOT * MAXL];

// ---------------------------------------------------------------------------
// Kernel 1: per-token importance.  One WARP per token.  W staged in smem.
// launch_bounds(256,4) -> <=64 regs so ptxas can front-batch all 8 LDG.128s
// (previous build chose regs=32, capping in-flight loads at ~4).
// ---------------------------------------------------------------------------
__global__ void __launch_bounds__(256, 4)
importance_kernel(const float* __restrict__ h,
                  const float* __restrict__ aw,
                  const float* __restrict__ W,
                  const float* __restrict__ b)
{
    __shared__ float4 s_W[DIM / 4];          // 16 KB

#pragma unroll
    for (int j = 0; j < 4; j++)
        s_W[threadIdx.x + j * 256] = ((const float4*)W)[threadIdx.x + j * 256];
    __syncthreads();

    int warp = (blockIdx.x * 256 + threadIdx.x) >> 5;   // token id 0..8191
    int lane = threadIdx.x & 31;

    const float4* __restrict__ hr = (const float4*)(h + (size_t)warp * DIM);

    float ssq = 0.f, dot = 0.f;
#pragma unroll 8
    for (int k = 0; k < 32; k++) {
        int i = lane + (k << 5);
        float4 hv = hr[i];
        float4 wv = s_W[i];
        ssq = fmaf(hv.x, hv.x, ssq); ssq = fmaf(hv.y, hv.y, ssq);
        ssq = fmaf(hv.z, hv.z, ssq); ssq = fmaf(hv.w, hv.w, ssq);
        dot = fmaf(hv.x, wv.x, dot); dot = fmaf(hv.y, wv.y, dot);
        dot = fmaf(hv.z, wv.z, dot); dot = fmaf(hv.w, wv.w, dot);
    }
#pragma unroll
    for (int off = 16; off > 0; off >>= 1) {
        ssq += __shfl_down_sync(0xffffffffu, ssq, off);
        dot += __shfl_down_sync(0xffffffffu, dot, off);
    }
    if (lane == 0) {
        float4 a4 = ((const float4*)aw)[warp];     // KS = 4 weights
        float ent = -(a4.x * logf(a4.x + 1e-8f) + a4.y * logf(a4.y + 1e-8f) +
                      a4.z * logf(a4.z + 1e-8f) + a4.w * logf(a4.w + 1e-8f));
        float sur = ent * (1.0f / 1.3862943611198906f);    // / log(4)
        float learned = 1.0f / (1.0f + expf(-(dot + b[0])));
        g_imp[warp] = sqrtf(ssq) * (1.0f + sur) + learned;
    }
}

// ---------------------------------------------------------------------------
// Kernel 2: exact top-1024 radix select (1 block, 1024 threads) + per-slot
// token lists via shared atomics (R9 structure, part of the 46.9us best).
// ---------------------------------------------------------------------------
__global__ void __launch_bounds__(1024)
select_kernel(const int* __restrict__ slot_idx)
{
    __shared__ unsigned s_keys[T_TOK];    // 32 KB
    __shared__ int      s_hist[256];
    __shared__ int      s_cnt[NSLOT];
    __shared__ unsigned s_prefix, s_pmask;
    __shared__ int      s_k;
    __shared__ int      s_wsum[32];

    int tid = threadIdx.x;
    if (tid < NSLOT) s_cnt[tid] = 0;

    // load keys (monotone float->uint transform)
#pragma unroll
    for (int j = 0; j < 8; j++) {
        int t = tid + j * 1024;
        unsigned u = __float_as_uint(g_imp[t]);
        u = (u & 0x80000000u) ? ~u : (u | 0x80000000u);
        s_keys[t] = u;
    }
    if (tid == 0) { s_prefix = 0u; s_pmask = 0u; s_k = TOPK; }
    __syncthreads();

    // 4-pass MSB->LSB byte radix select for the 1024th-largest key
    for (int shift = 24; shift >= 0; shift -= 8) {
        if (tid < 256) s_hist[tid] = 0;
        __syncthreads();
        unsigned pmask = s_pmask, prefix = s_prefix;
#pragma unroll
        for (int j = 0; j < 8; j++) {
            unsigned u = s_keys[tid + j * 1024];
            if ((u & pmask) == prefix) atomicAdd(&s_hist[(u >> shift) & 255], 1);
        }
        __syncthreads();
        // warp 0: parallel suffix-scan over 256 buckets (8 per lane)
        if (tid < 32) {
            int k = s_k;
            int h8[8];
            int tot = 0;
#pragma unroll
            for (int j = 0; j < 8; j++) { h8[j] = s_hist[tid * 8 + j]; tot += h8[j]; }
            int suf = tot;
#pragma unroll
            for (int off = 1; off < 32; off <<= 1) {
                int n = __shfl_down_sync(0xffffffffu, suf, off);
                if (tid + off < 32) suf += n;
            }
            int tail = suf - tot;   // sum of buckets in lanes > tid
            int sfx[8];
            int s = tail;
#pragma unroll
            for (int j = 7; j >= 0; j--) { s += h8[j]; sfx[j] = s; }
#pragma unroll
            for (int j = 0; j < 8; j++) {
                int above = sfx[j] - h8[j];
                if (sfx[j] >= k && above < k) {
                    s_prefix = prefix | ((unsigned)(tid * 8 + j) << shift);
                    s_pmask  = pmask | (0xFFu << shift);
                    s_k      = k - above;
                }
            }
        }
        __syncthreads();
    }
    unsigned thr = s_prefix;
    int need_eq  = s_k;         // #keys == thr to take (in token-index order)

    // block exclusive scan of per-thread equal-to-threshold counts
    int base = tid * 8;
    int loc_eq = 0;
#pragma unroll
    for (int j = 0; j < 8; j++) loc_eq += (s_keys[base + j] == thr);

    int lane = tid & 31, wid = tid >> 5;
    int inc = loc_eq;
#pragma unroll
    for (int off = 1; off < 32; off <<= 1) {
        int n = __shfl_up_sync(0xffffffffu, inc, off);
        if (lane >= off) inc += n;
    }
    if (lane == 31) s_wsum[wid] = inc;
    __syncthreads();
    if (wid == 0) {
        int v = s_wsum[lane];
        int iv = v;
#pragma unroll
        for (int off = 1; off < 32; off <<= 1) {
            int n = __shfl_up_sync(0xffffffffu, iv, off);
            if (lane >= off) iv += n;
        }
        s_wsum[lane] = iv - v;    // exclusive warp-prefix
    }
    __syncthreads();
    int run = s_wsum[wid] + (inc - loc_eq);   // exclusive prefix of equals

    // scatter selected tokens into per-slot lists
#pragma unroll
    for (int j = 0; j < 8; j++) {
        int t = base + j;
        unsigned u = s_keys[t];
        bool sel = (u > thr);
        if (u == thr) { sel = (run < need_eq); run++; }
        if (sel) {
            int4 sl = ((const int4*)slot_idx)[t];
            int ss[4] = { sl.x, sl.y, sl.z, sl.w };
#pragma unroll
            for (int q = 0; q < KS; q++) {
                int slot = ss[q];
                int pos = atomicAdd(&s_cnt[slot], 1);
                g_slot_list[slot * MAXL + pos] = t;
            }
        }
    }
    __syncthreads();
    if (tid < NSLOT) g_slot_cnt[tid] = s_cnt[tid];
}

// ---------------------------------------------------------------------------
// Kernel 3: gather-aggregate per slot + EMA write (R9 float4 structure,
// measured 13.2us) + TOKEN LIST STAGED IN SHARED MEMORY up-front, breaking
// the list-load -> gather dependent chain inside the loop.
// grid = (8 chunks of 512 floats, 128 slots), 128 threads, float4/thread.
// ---------------------------------------------------------------------------
__global__ void __launch_bounds__(128)
aggregate_kernel(const float* __restrict__ h,
                 const float* __restrict__ mem,
                 float* __restrict__ out)
{
    __shared__ int s_lst[MAXL];          // 16 KB worst case

    int slot = blockIdx.y;
    int d = blockIdx.x * 512 + threadIdx.x * 4;
    int cnt = g_slot_cnt[slot];

    // stage the whole list coalesced
    for (int i = threadIdx.x; i < cnt; i += 128)
        s_lst[i] = g_slot_list[slot * MAXL + i];
    __syncthreads();

    float4 acc0 = make_float4(0.f, 0.f, 0.f, 0.f);
    float4 acc1 = make_float4(0.f, 0.f, 0.f, 0.f);
    float4 acc2 = make_float4(0.f, 0.f, 0.f, 0.f);
    float4 acc3 = make_float4(0.f, 0.f, 0.f, 0.f);
    int i = 0;
    for (; i + 7 < cnt; i += 8) {
        int t0 = s_lst[i],     t1 = s_lst[i + 1], t2 = s_lst[i + 2], t3 = s_lst[i + 3];
        int t4 = s_lst[i + 4], t5 = s_lst[i + 5], t6 = s_lst[i + 6], t7 = s_lst[i + 7];
        float4 v0 = *(const float4*)(h + (size_t)t0 * DIM + d);
        float4 v1 = *(const float4*)(h + (size_t)t1 * DIM + d);
        float4 v2 = *(const float4*)(h + (size_t)t2 * DIM + d);
        float4 v3 = *(const float4*)(h + (size_t)t3 * DIM + d);
        float4 v4 = *(const float4*)(h + (size_t)t4 * DIM + d);
        float4 v5 = *(const float4*)(h + (size_t)t5 * DIM + d);
        float4 v6 = *(const float4*)(h + (size_t)t6 * DIM + d);
        float4 v7 = *(const float4*)(h + (size_t)t7 * DIM + d);
        acc0.x += v0.x + v1.x; acc0.y += v0.y + v1.y;
        acc0.z += v0.z + v1.z; acc0.w += v0.w + v1.w;
        acc1.x += v2.x + v3.x; acc1.y += v2.y + v3.y;
        acc1.z += v2.z + v3.z; acc1.w += v2.w + v3.w;
        acc2.x += v4.x + v5.x; acc2.y += v4.y + v5.y;
        acc2.z += v4.z + v5.z; acc2.w += v4.w + v5.w;
        acc3.x += v6.x + v7.x; acc3.y += v6.y + v7.y;
        acc3.z += v6.z + v7.z; acc3.w += v6.w + v7.w;
    }
    for (; i < cnt; i++) {
        int t0 = s_lst[i];
        float4 a = *(const float4*)(h + (size_t)t0 * DIM + d);
        acc0.x += a.x; acc0.y += a.y; acc0.z += a.z; acc0.w += a.w;
    }
    acc0.x += acc1.x + acc2.x + acc3.x;
    acc0.y += acc1.y + acc2.y + acc3.y;
    acc0.z += acc1.z + acc2.z + acc3.z;
    acc0.w += acc1.w + acc2.w + acc3.w;

    float4 cur = *(const float4*)(mem + (size_t)slot * DIM + d);
    float4 o;
    if (cnt > 0) {
        float inv = 1.0f / (float)cnt;
        o.x = fmaf(0.1f * inv, acc0.x, 0.9f * cur.x);
        o.y = fmaf(0.1f * inv, acc0.y, 0.9f * cur.y);
        o.z = fmaf(0.1f * inv, acc0.z, 0.9f * cur.z);
        o.w = fmaf(0.1f * inv, acc0.w, 0.9f * cur.w);
    } else {
        o = cur;
    }
    *(float4*)(out + (size_t)slot * DIM + d) = o;
}

// ---------------------------------------------------------------------------
extern "C" void kernel_launch(void* const* d_in, const int* in_sizes, int n_in,
                              void* d_out, int out_size)
{
    const float* h   = (const float*)d_in[0];   // hidden_states [8192,4096]
    const float* aw  = (const float*)d_in[1];   // attention_weights [8192,4]
    const float* mem = (const float*)d_in[2];   // memory [1,128,4096]
    const float* W   = (const float*)d_in[3];   // W_imp [1,4096]
    const float* b   = (const float*)d_in[4];   // b_imp [1]
    const int*   si  = (const int*)d_in[5];     // slot_indices [8192,4]
    float* out = (float*)d_out;                 // [1,128,4096]

    importance_kernel<<<T_TOK / 8, 256>>>(h, aw, W, b);   // 1 warp / token
    select_kernel<<<1, 1024>>>(si);
    aggregate_kernel<<<dim3(8, NSLOT), 128>>>(h, mem, out);
}

// round 17
// speedup vs baseline: 1.1699x; 1.1699x over previous
#include <cuda_runtime.h>
#include <cuda_bf16.h>

// Problem constants (fixed by setup_inputs)
#define T_TOK  8192
#define DIM    4096
#define KS     4
#define NSLOT  128
#define TOPK   1024
#define MAXL   4096   // worst case: all TOPK*KS writes land on one slot

// Scratch (no allocations allowed -> __device__ globals)
__device__ float g_imp[T_TOK];
__device__ int   g_slot_cnt[NSLOT];
__device__ int   g_slot_list[NSLOT * MAXL];

// ---------------------------------------------------------------------------
// Kernel 1: per-token importance.  One WARP per token (exact R9 structure:
// measured 25.3us @ 69% DRAM, regs=32, occ 77%).
// ---------------------------------------------------------------------------
__global__ void __launch_bounds__(256)
importance_kernel(const float* __restrict__ h,
                  const float* __restrict__ aw,
                  const float* __restrict__ W,
                  const float* __restrict__ b)
{
    __shared__ float4 s_W[DIM / 4];          // 16 KB

#pragma unroll
    for (int j = 0; j < 4; j++)
        s_W[threadIdx.x + j * 256] = ((const float4*)W)[threadIdx.x + j * 256];
    __syncthreads();

    int warp = (blockIdx.x * 256 + threadIdx.x) >> 5;   // token id 0..8191
    int lane = threadIdx.x & 31;

    const float4* __restrict__ hr = (const float4*)(h + (size_t)warp * DIM);

    float ssq = 0.f, dot = 0.f;
#pragma unroll 8
    for (int k = 0; k < 32; k++) {
        int i = lane + (k << 5);
        float4 hv = hr[i];
        float4 wv = s_W[i];
        ssq = fmaf(hv.x, hv.x, ssq); ssq = fmaf(hv.y, hv.y, ssq);
        ssq = fmaf(hv.z, hv.z, ssq); ssq = fmaf(hv.w, hv.w, ssq);
        dot = fmaf(hv.x, wv.x, dot); dot = fmaf(hv.y, wv.y, dot);
        dot = fmaf(hv.z, wv.z, dot); dot = fmaf(hv.w, wv.w, dot);
    }
#pragma unroll
    for (int off = 16; off > 0; off >>= 1) {
        ssq += __shfl_down_sync(0xffffffffu, ssq, off);
        dot += __shfl_down_sync(0xffffffffu, dot, off);
    }
    if (lane == 0) {
        float4 a4 = ((const float4*)aw)[warp];     // KS = 4 weights
        float ent = -(a4.x * logf(a4.x + 1e-8f) + a4.y * logf(a4.y + 1e-8f) +
                      a4.z * logf(a4.z + 1e-8f) + a4.w * logf(a4.w + 1e-8f));
        float sur = ent * (1.0f / 1.3862943611198906f);    // / log(4)
        float learned = 1.0f / (1.0f + expf(-(dot + b[0])));
        g_imp[warp] = sqrtf(ssq) * (1.0f + sur) + learned;
    }
}

// ---------------------------------------------------------------------------
// Kernel 2: exact top-1024 radix select (1 block, 1024 threads) + per-slot
// token lists via shared atomics (exact R9 structure).
// ---------------------------------------------------------------------------
__global__ void __launch_bounds__(1024)
select_kernel(const int* __restrict__ slot_idx)
{
    __shared__ unsigned s_keys[T_TOK];    // 32 KB
    __shared__ int      s_hist[256];
    __shared__ int      s_cnt[NSLOT];
    __shared__ unsigned s_prefix, s_pmask;
    __shared__ int      s_k;
    __shared__ int      s_wsum[32];

    int tid = threadIdx.x;
    if (tid < NSLOT) s_cnt[tid] = 0;

    // load keys (monotone float->uint transform)
#pragma unroll
    for (int j = 0; j < 8; j++) {
        int t = tid + j * 1024;
        unsigned u = __float_as_uint(g_imp[t]);
        u = (u & 0x80000000u) ? ~u : (u | 0x80000000u);
        s_keys[t] = u;
    }
    if (tid == 0) { s_prefix = 0u; s_pmask = 0u; s_k = TOPK; }
    __syncthreads();

    // 4-pass MSB->LSB byte radix select for the 1024th-largest key
    for (int shift = 24; shift >= 0; shift -= 8) {
        if (tid < 256) s_hist[tid] = 0;
        __syncthreads();
        unsigned pmask = s_pmask, prefix = s_prefix;
#pragma unroll
        for (int j = 0; j < 8; j++) {
            unsigned u = s_keys[tid + j * 1024];
            if ((u & pmask) == prefix) atomicAdd(&s_hist[(u >> shift) & 255], 1);
        }
        __syncthreads();
        // warp 0: parallel suffix-scan over 256 buckets (8 per lane)
        if (tid < 32) {
            int k = s_k;
            int h8[8];
            int tot = 0;
#pragma unroll
            for (int j = 0; j < 8; j++) { h8[j] = s_hist[tid * 8 + j]; tot += h8[j]; }
            int suf = tot;
#pragma unroll
            for (int off = 1; off < 32; off <<= 1) {
                int n = __shfl_down_sync(0xffffffffu, suf, off);
                if (tid + off < 32) suf += n;
            }
            int tail = suf - tot;   // sum of buckets in lanes > tid
            int sfx[8];
            int s = tail;
#pragma unroll
            for (int j = 7; j >= 0; j--) { s += h8[j]; sfx[j] = s; }
#pragma unroll
            for (int j = 0; j < 8; j++) {
                int above = sfx[j] - h8[j];
                if (sfx[j] >= k && above < k) {
                    s_prefix = prefix | ((unsigned)(tid * 8 + j) << shift);
                    s_pmask  = pmask | (0xFFu << shift);
                    s_k      = k - above;
                }
            }
        }
        __syncthreads();
    }
    unsigned thr = s_prefix;
    int need_eq  = s_k;         // #keys == thr to take (in token-index order)

    // block exclusive scan of per-thread equal-to-threshold counts
    int base = tid * 8;
    int loc_eq = 0;
#pragma unroll
    for (int j = 0; j < 8; j++) loc_eq += (s_keys[base + j] == thr);

    int lane = tid & 31, wid = tid >> 5;
    int inc = loc_eq;
#pragma unroll
    for (int off = 1; off < 32; off <<= 1) {
        int n = __shfl_up_sync(0xffffffffu, inc, off);
        if (lane >= off) inc += n;
    }
    if (lane == 31) s_wsum[wid] = inc;
    __syncthreads();
    if (wid == 0) {
        int v = s_wsum[lane];
        int iv = v;
#pragma unroll
        for (int off = 1; off < 32; off <<= 1) {
            int n = __shfl_up_sync(0xffffffffu, iv, off);
            if (lane >= off) iv += n;
        }
        s_wsum[lane] = iv - v;    // exclusive warp-prefix
    }
    __syncthreads();
    int run = s_wsum[wid] + (inc - loc_eq);   // exclusive prefix of equals

    // scatter selected tokens into per-slot lists
#pragma unroll
    for (int j = 0; j < 8; j++) {
        int t = base + j;
        unsigned u = s_keys[t];
        bool sel = (u > thr);
        if (u == thr) { sel = (run < need_eq); run++; }
        if (sel) {
            int4 sl = ((const int4*)slot_idx)[t];
            int ss[4] = { sl.x, sl.y, sl.z, sl.w };
#pragma unroll
            for (int q = 0; q < KS; q++) {
                int slot = ss[q];
                int pos = atomicAdd(&s_cnt[slot], 1);
                g_slot_list[slot * MAXL + pos] = t;
            }
        }
    }
    __syncthreads();
    if (tid < NSLOT) g_slot_cnt[tid] = s_cnt[tid];
}

// ---------------------------------------------------------------------------
// Kernel 3: gather-aggregate per slot + EMA write.
// 512 threads = 4 TOKEN-GROUPS x 128 d-threads per block.  Group g sums
// tokens i === g (mod 4) with 2-way unroll -> per-warp dependent chain is
// cnt/8 latency-steps instead of cnt/2.  Cross-group smem reduction (6KB).
// grid = (8 chunks of 512 floats, 128 slots) = 1024 blocks.
// ---------------------------------------------------------------------------
__global__ void __launch_bounds__(512)
aggregate_kernel(const float* __restrict__ h,
                 const float* __restrict__ mem,
                 float* __restrict__ out)
{
    __shared__ float4 s_red[3][128];     // partials of groups 1..3 (6 KB)

    int slot = blockIdx.y;
    int grp  = threadIdx.x >> 7;         // 0..3 token-group
    int gtid = threadIdx.x & 127;        // d-thread within group
    int d = blockIdx.x * 512 + gtid * 4;
    int cnt = g_slot_cnt[slot];
    const int* __restrict__ lst = &g_slot_list[slot * MAXL];

    float4 acc0 = make_float4(0.f, 0.f, 0.f, 0.f);
    float4 acc1 = make_float4(0.f, 0.f, 0.f, 0.f);

    int i = grp;
    // pairs (i, i+4) both in range, i stepping by 8 within this group's residue
    for (; i + 4 < cnt; i += 8) {
        int t0 = lst[i], t1 = lst[i + 4];
        float4 v0 = *(const float4*)(h + (size_t)t0 * DIM + d);
        float4 v1 = *(const float4*)(h + (size_t)t1 * DIM + d);
        acc0.x += v0.x; acc0.y += v0.y; acc0.z += v0.z; acc0.w += v0.w;
        acc1.x += v1.x; acc1.y += v1.y; acc1.z += v1.z; acc1.w += v1.w;
    }
    if (i < cnt) {
        int t0 = lst[i];
        float4 v0 = *(const float4*)(h + (size_t)t0 * DIM + d);
        acc0.x += v0.x; acc0.y += v0.y; acc0.z += v0.z; acc0.w += v0.w;
    }
    acc0.x += acc1.x; acc0.y += acc1.y; acc0.z += acc1.z; acc0.w += acc1.w;

    if (grp > 0) s_red[grp - 1][gtid] = acc0;
    __syncthreads();

    if (grp == 0) {
        float4 p0 = s_red[0][gtid], p1 = s_red[1][gtid], p2 = s_red[2][gtid];
        acc0.x += (p0.x + p1.x) + p2.x;
        acc0.y += (p0.y + p1.y) + p2.y;
        acc0.z += (p0.z + p1.z) + p2.z;
        acc0.w += (p0.w + p1.w) + p2.w;

        float4 cur = *(const float4*)(mem + (size_t)slot * DIM + d);
        float4 o;
        if (cnt > 0) {
            float inv = 1.0f / (float)cnt;
            o.x = fmaf(0.1f * inv, acc0.x, 0.9f * cur.x);
            o.y = fmaf(0.1f * inv, acc0.y, 0.9f * cur.y);
            o.z = fmaf(0.1f * inv, acc0.z, 0.9f * cur.z);
            o.w = fmaf(0.1f * inv, acc0.w, 0.9f * cur.w);
        } else {
            o = cur;
        }
        *(float4*)(out + (size_t)slot * DIM + d) = o;
    }
}

// ---------------------------------------------------------------------------
extern "C" void kernel_launch(void* const* d_in, const int* in_sizes, int n_in,
                              void* d_out, int out_size)
{
    const float* h   = (const float*)d_in[0];   // hidden_states [8192,4096]
    const float* aw  = (const float*)d_in[1];   // attention_weights [8192,4]
    const float* mem = (const float*)d_in[2];   // memory [1,128,4096]
    const float* W   = (const float*)d_in[3];   // W_imp [1,4096]
    const float* b   = (const float*)d_in[4];   // b_imp [1]
    const int*   si  = (const int*)d_in[5];     // slot_indices [8192,4]
    float* out = (float*)d_out;                 // [1,128,4096]

    importance_kernel<<<T_TOK / 8, 256>>>(h, aw, W, b);   // 1 warp / token
    select_kernel<<<1, 1024>>>(si);
    aggregate_kernel<<<dim3(8, NSLOT), 512>>>(h, mem, out);
}